// round 3
// baseline (speedup 1.0000x reference)
#include <cuda_runtime.h>
#include <cuda_fp16.h>

#define N_ANGLES  180
#define N_DET     256
#define IMG       256
#define T_STEPS   256
#define PITCH     262               // halves per row; 131 words/row == 3 mod 32 (bank decorrelation)
#define G_ANGLES  5
#define N_GROUPS  (N_ANGLES / G_ANGLES)   // 36
#define THREADS   640
#define SMEM_BYTES (IMG * PITCH * 2)      // 134144 B

__device__ __forceinline__ float fetch_guard(const __half* __restrict__ simg, int ix, int iy) {
    bool valid = ((unsigned)ix < (unsigned)IMG) && ((unsigned)iy < (unsigned)IMG);
    int xc = min(IMG - 1, max(0, ix));
    int yc = min(IMG - 1, max(0, iy));
    float v = __half2float(simg[yc * PITCH + xc]);
    return valid ? v : 0.0f;
}

__device__ __forceinline__ float sample_generic(const __half* __restrict__ simg, float x, float y) {
    float fx = floorf(x), fy = floorf(y);
    int xi = (int)fx, yi = (int)fy;
    float wx = x - fx, wy = y - fy;
    float v00 = fetch_guard(simg, xi,     yi);
    float v01 = fetch_guard(simg, xi + 1, yi);
    float v10 = fetch_guard(simg, xi,     yi + 1);
    float v11 = fetch_guard(simg, xi + 1, yi + 1);
    float r0 = fmaf(wx, v01 - v00, v00);
    float r1 = fmaf(wx, v11 - v10, v10);
    return fmaf(wy, r1 - r0, r0);
}

// Intersect t-interval [t0,t1] with { t : lo <= p0 + t*d <= hi }
__device__ __forceinline__ void slab(float p0, float d, float lo, float hi,
                                     float& t0, float& t1) {
    if (fabsf(d) > 1e-12f) {
        float inv = 1.0f / d;
        float a = (lo - p0) * inv;
        float b = (hi - p0) * inv;
        t0 = fmaxf(t0, fminf(a, b));
        t1 = fminf(t1, fmaxf(a, b));
    } else if (p0 < lo || p0 > hi) {
        t0 = 1.0e9f; t1 = -1.0e9f;
    }
}

__global__ __launch_bounds__(THREADS, 1)
void radon_fwd_kernel(const float* __restrict__ in, float* __restrict__ out) {
    extern __shared__ __half simg[];

    int batch = blockIdx.x / N_GROUPS;
    int grp   = blockIdx.x % N_GROUPS;

    // ---- Stage this batch's image into SMEM as fp16 (rel err <= 2^-11) ----
    const float4* img4 = (const float4*)(in + (size_t)batch * IMG * IMG);
    for (int i = threadIdx.x; i < IMG * IMG / 4; i += THREADS) {
        float4 v = img4[i];
        int row = i >> 6;            // 64 float4 per 256-wide row
        int col = (i & 63) << 2;
        __half2* p = (__half2*)(simg + row * PITCH + col);
        p[0] = __floats2half2_rn(v.x, v.y);
        p[1] = __floats2half2_rn(v.z, v.w);
    }
    __syncthreads();

    // ---- Each thread integrates full rays: 5 angles x 256 detectors ----
    for (int r = threadIdx.x; r < G_ANGLES * N_DET; r += THREADS) {
        int aL = r >> 8;
        int d  = r & 255;
        int a  = grp * G_ANGLES + aL;

        float theta = (float)a * 0.017453292519943295f;   // pi/180
        float sn, cs;
        sincosf(theta, &sn, &cs);
        float sd = (float)d - 127.5f;
        // x(k) = X0 + k*dx, y(k) = Y0 + k*dy  with t_k = k - 127.5
        float X0 = fmaf(sd, cs, fmaf(127.5f, sn, 127.5f));
        float Y0 = fmaf(sd, sn, fmaf(-127.5f, cs, 127.5f));
        float dx = -sn, dy = cs;

        // Outer box: any nonzero contribution. Interior box: all 4 taps valid.
        float t0 = 0.0f, t1 = (float)(T_STEPS - 1);
        float ti0 = 0.0f, ti1 = (float)(T_STEPS - 1);
        slab(X0, dx, -1.001f, 256.001f, t0, t1);
        slab(Y0, dy, -1.001f, 256.001f, t0, t1);
        slab(X0, dx, 0.002f, 254.998f, ti0, ti1);
        slab(Y0, dy, 0.002f, 254.998f, ti0, ti1);
        t0 = fmaxf(t0, 0.0f);  t1 = fminf(t1, 255.0f);
        ti0 = fmaxf(ti0, 0.0f); ti1 = fminf(ti1, 255.0f);

        int ko0 = max(0, (int)ceilf(t0));
        int ko1 = min(T_STEPS - 1, (int)floorf(t1));
        int ki0 = max(ko0, (int)ceilf(ti0));
        int ki1 = min(ko1, (int)floorf(ti1));
        if (ki0 > ki1) { ki0 = ko1 + 1; ki1 = ko1; }  // empty interior -> all edge

        float acc = 0.0f;

        // leading edge band (guarded)
        int e1end = min(ki0 - 1, ko1);
        for (int k = ko0; k <= e1end; ++k) {
            float x = fmaf((float)k, dx, X0);
            float y = fmaf((float)k, dy, Y0);
            acc += sample_generic(simg, x, y);
        }

        // interior fast loop: unguarded 4-tap bilinear from SMEM
        float kf = (float)ki0;
        #pragma unroll 4
        for (int k = ki0; k <= ki1; ++k) {
            float x = fmaf(kf, dx, X0);
            float y = fmaf(kf, dy, Y0);
            kf += 1.0f;
            float fx = floorf(x), fy = floorf(y);
            int xi = (int)fx, yi = (int)fy;
            float wx = x - fx, wy = y - fy;
            const __half* p = simg + yi * PITCH + xi;
            float v00 = __half2float(p[0]);
            float v01 = __half2float(p[1]);
            float v10 = __half2float(p[PITCH]);
            float v11 = __half2float(p[PITCH + 1]);
            float r0 = fmaf(wx, v01 - v00, v00);
            float r1 = fmaf(wx, v11 - v10, v10);
            acc = fmaf(wy, r1 - r0, acc + r0);
        }

        // trailing edge band (guarded)
        for (int k = ki1 + 1; k <= ko1; ++k) {
            float x = fmaf((float)k, dx, X0);
            float y = fmaf((float)k, dy, Y0);
            acc += sample_generic(simg, x, y);
        }

        out[((size_t)batch * N_ANGLES + a) * N_DET + d] = acc;
    }
}

extern "C" void kernel_launch(void* const* d_in, const int* in_sizes, int n_in,
                              void* d_out, int out_size) {
    (void)in_sizes; (void)n_in; (void)out_size;
    cudaFuncSetAttribute(radon_fwd_kernel,
                         cudaFuncAttributeMaxDynamicSharedMemorySize, SMEM_BYTES);
    radon_fwd_kernel<<<8 * N_GROUPS, THREADS, SMEM_BYTES>>>(
        (const float*)d_in[0], (float*)d_out);
}

// round 8
// speedup vs baseline: 1.0287x; 1.0287x over previous
#include <cuda_runtime.h>
#include <cuda_fp16.h>

#define N_ANGLES  180
#define N_DET     256
#define IMG       256
#define G_ANGLES  2
#define N_GROUPS  (N_ANGLES / G_ANGLES)   // 90
#define N_SLABS   4
#define SLAB_H    64
#define THREADS   256
#define PITCH     258                     // halves/row = 129 words == 1 (mod 32): conflict-free at all angles
#define LROWS     67                      // slab rows 64 + guard rows (-1, +64, +65)
#define SMEM_BYTES (LROWS * PITCH * 2)    // 34572 B -> 6 blocks/SM
#define OUT_ELEMS (8 * N_ANGLES * N_DET)

__device__ float g_scratch[N_SLABS][OUT_ELEMS];   // slab partials (5.9 MB)

// Clamp before float->int: boundary products reach +/-3e9 at theta~90deg; raw
// (int)ceilf saturates and the subsequent +/-1 WRAPS (R7 crash). k only needs
// [0,255], so +/-1e6 preserves all comparisons and cross-slab consistency.
__device__ __forceinline__ int ifloor_c(float v) {
    return (int)floorf(fminf(fmaxf(v, -1.0e6f), 1.0e6f));
}
__device__ __forceinline__ int iceil_c(float v) {
    return (int)ceilf(fminf(fmaxf(v, -1.0e6f), 1.0e6f));
}

__device__ __forceinline__ void slab_clip(float p0, float d, float lo, float hi,
                                          float& t0, float& t1) {
    if (fabsf(d) > 1e-12f) {
        float inv = 1.0f / d;
        float a = (lo - p0) * inv;
        float b = (hi - p0) * inv;
        t0 = fmaxf(t0, fminf(a, b));
        t1 = fminf(t1, fmaxf(a, b));
    } else if (p0 < lo || p0 > hi) {
        t0 = 1.0e6f; t1 = -1.0e6f;
    }
}

// Edge-band sample: rows are always valid (slab guard rows); only x needs guarding.
__device__ __forceinline__ float edge_sample(const __half* __restrict__ sb,
                                             float X0, float Y0, float dx, float dy, int k) {
    float x = fmaf((float)k, dx, X0);
    float y = fmaf((float)k, dy, Y0);
    int xi = __float2int_rd(x);
    int yi = __float2int_rd(y);
    float wx = x - (float)xi;
    float wy = y - (float)yi;
    const __half* p = sb + yi * PITCH;
    int x0c = min(255, max(0, xi));
    int x1c = min(255, max(0, xi + 1));
    bool g0 = ((unsigned)xi < 256u);
    bool g1 = ((unsigned)(xi + 1) < 256u);
    float v00 = g0 ? __half2float(p[x0c]) : 0.0f;
    float v01 = g1 ? __half2float(p[x1c]) : 0.0f;
    float v10 = g0 ? __half2float(p[x0c + PITCH]) : 0.0f;
    float v11 = g1 ? __half2float(p[x1c + PITCH]) : 0.0f;
    float r0 = fmaf(wx, v01 - v00, v00);
    float r1 = fmaf(wx, v11 - v10, v10);
    return fmaf(wy, r1 - r0, r0);
}

__global__ __launch_bounds__(THREADS, 6)
void radon_slab_kernel(const float* __restrict__ in) {
    extern __shared__ __half simg[];

    int b     = blockIdx.x;
    int slab  = b & 3;                 // low bits: spread the 4 slabs of one image across SMs
    int rem   = b >> 2;
    int grp   = rem % N_GROUPS;
    int batch = rem / N_GROUPS;
    int row_lo = slab * SLAB_H - 1;    // first stored global row

    // ---- Stage slab rows [row_lo, row_lo+66] as fp16 (out-of-range rows = 0) ----
    const float* img = in + (size_t)batch * IMG * IMG;
    for (int i = threadIdx.x; i < LROWS * (IMG / 4); i += THREADS) {
        int L  = i >> 6;               // 64 float4 groups per 256-wide row
        int c4 = (i & 63) << 2;
        int g  = row_lo + L;
        __half2 h0, h1;
        if ((unsigned)g < (unsigned)IMG) {
            float4 v = *(const float4*)(img + g * IMG + c4);
            h0 = __floats2half2_rn(v.x, v.y);
            h1 = __floats2half2_rn(v.z, v.w);
        } else {
            h0 = __floats2half2_rn(0.0f, 0.0f);
            h1 = h0;
        }
        __half2* p = (__half2*)(simg + L * PITCH + c4);
        p[0] = h0; p[1] = h1;
    }
    __syncthreads();

    // sb + yi*PITCH is valid for all yi this slab can see (guard rows cover +/-1 misassignment)
    const __half* sb = simg - row_lo * PITCH;

    for (int r = threadIdx.x; r < G_ANGLES * N_DET; r += THREADS) {
        int aL = r >> 8;
        int d  = r & 255;
        int a  = grp * G_ANGLES + aL;

        float theta = (float)a * 0.017453292519943295f;   // pi/180
        float sn, cs;
        sincosf(theta, &sn, &cs);
        float sd = (float)d - 127.5f;
        float X0 = fmaf(sd, cs, fmaf(127.5f, sn, 127.5f));
        float Y0 = fmaf(sd, sn, fmaf(-127.5f, cs, 127.5f));
        float dx = -sn, dy = cs;

        // Outer nonzero-contribution range; margins keep yi in [-1,255], so rows stay in-slab
        float t0 = 0.0f, t1 = 255.0f;
        slab_clip(X0, dx, -0.999f, 255.999f, t0, t1);
        slab_clip(Y0, dy, -0.999f, 255.999f, t0, t1);
        int k0 = max(0,   iceil_c(t0));
        int k1 = min(255, ifloor_c(t1));

        // Exact y-slab partition: adjacent slabs evaluate the SAME clamped float
        // expression, so every k is claimed by exactly one slab; +/-1-row guard
        // absorbs the tiny y-error at the boundary k.
        if (fabsf(dy) < 1e-12f) {
            int ch = min(3, max(0, (int)floorf(Y0 * (1.0f / 64.0f))));
            if (ch != slab) { k0 = 1; k1 = 0; }
        } else {
            float inv = 1.0f / dy;
            if (dy > 0.0f) {
                if (slab > 0) k0 = max(k0, iceil_c(((float)(slab * SLAB_H) - Y0) * inv));
                if (slab < 3) k1 = min(k1, iceil_c(((float)((slab + 1) * SLAB_H) - Y0) * inv) - 1);
            } else {
                if (slab < 3) k0 = max(k0, ifloor_c(((float)((slab + 1) * SLAB_H) - Y0) * inv) + 1);
                if (slab > 0) k1 = min(k1, ifloor_c(((float)(slab * SLAB_H) - Y0) * inv));
            }
        }

        // x-interior: all 4 taps valid in x -> guard-free fast loop
        float ti0 = 0.0f, ti1 = 255.0f;
        slab_clip(X0, dx, 0.002f, 254.998f, ti0, ti1);
        int ki0 = max(k0, iceil_c(ti0));
        int ki1 = min(k1, ifloor_c(ti1));
        if (ki0 > ki1) { ki0 = k1 + 1; ki1 = k1; }   // empty interior -> all edge

        float acc = 0.0f;

        // leading edge band (x-guarded only)
        int e1 = min(ki0 - 1, k1);
        for (int k = k0; k <= e1; ++k)
            acc += edge_sample(sb, X0, Y0, dx, dy, k);

        // interior fast loop: completely unguarded
        float kf = (float)ki0;
        #pragma unroll 4
        for (int k = ki0; k <= ki1; ++k) {
            float x = fmaf(kf, dx, X0);
            float y = fmaf(kf, dy, Y0);
            kf += 1.0f;
            int xi = __float2int_rd(x);
            int yi = __float2int_rd(y);
            float wx = x - (float)xi;
            float wy = y - (float)yi;
            const __half* p = sb + yi * PITCH + xi;
            float v00 = __half2float(p[0]);
            float v01 = __half2float(p[1]);
            float v10 = __half2float(p[PITCH]);
            float v11 = __half2float(p[PITCH + 1]);
            float r0 = fmaf(wx, v01 - v00, v00);
            float r1 = fmaf(wx, v11 - v10, v10);
            acc = fmaf(wy, r1 - r0, acc + r0);
        }

        // trailing edge band
        int e2 = max(ki1 + 1, k0);
        for (int k = e2; k <= k1; ++k)
            acc += edge_sample(sb, X0, Y0, dx, dy, k);

        g_scratch[slab][((size_t)batch * N_ANGLES + a) * N_DET + d] = acc;
    }
}

__global__ void radon_reduce_kernel(float* __restrict__ out) {
    int i = blockIdx.x * blockDim.x + threadIdx.x;
    if (i < OUT_ELEMS) {
        out[i] = (g_scratch[0][i] + g_scratch[1][i]) +
                 (g_scratch[2][i] + g_scratch[3][i]);
    }
}

extern "C" void kernel_launch(void* const* d_in, const int* in_sizes, int n_in,
                              void* d_out, int out_size) {
    (void)in_sizes; (void)n_in; (void)out_size;
    radon_slab_kernel<<<8 * N_GROUPS * N_SLABS, THREADS, SMEM_BYTES>>>((const float*)d_in[0]);
    radon_reduce_kernel<<<(OUT_ELEMS + 511) / 512, 512>>>((float*)d_out);
}

// round 12
// speedup vs baseline: 1.0538x; 1.0245x over previous
#include <cuda_runtime.h>
#include <cuda_fp16.h>

#define N_ANGLES  180
#define N_DET     256
#define IMG       256
#define G_ANGLES  2
#define N_GROUPS  (N_ANGLES / G_ANGLES)   // 90
#define N_SLABS   4
#define SLAB_H    64
#define THREADS   256
#define PITCH     258                     // halves/row = 129 words == 1 (mod 32): conflict-free
#define LROWS     67                      // slab rows 64 + guard rows (-1, +64, +65)
#define SMEM_BYTES (LROWS * PITCH * 2)    // 34572 B
#define OUT_ELEMS (8 * N_ANGLES * N_DET)

__device__ float g_scratch[N_SLABS][OUT_ELEMS];   // slab partials (5.9 MB)

// Clamp before float->int: raw cvt saturates and later +/-1 wraps (R7 crash).
__device__ __forceinline__ int ifloor_c(float v) {
    return (int)floorf(fminf(fmaxf(v, -1.0e6f), 1.0e6f));
}
__device__ __forceinline__ int iceil_c(float v) {
    return (int)ceilf(fminf(fmaxf(v, -1.0e6f), 1.0e6f));
}

__device__ __forceinline__ void slab_clip(float p0, float d, float lo, float hi,
                                          float& t0, float& t1) {
    if (fabsf(d) > 1e-12f) {
        float inv = 1.0f / d;
        float a = (lo - p0) * inv;
        float b = (hi - p0) * inv;
        t0 = fmaxf(t0, fminf(a, b));
        t1 = fminf(t1, fmaxf(a, b));
    } else if (p0 < lo || p0 > hi) {
        t0 = 1.0e6f; t1 = -1.0e6f;
    }
}

// Edge-band sample in EFFECTIVE coords: rows (eff-y) always in-slab via guard
// rows; only eff-x needs guarding (zero outside, symmetric in x/y so valid
// for both orientations).
__device__ __forceinline__ float edge_sample(const __half* __restrict__ sb,
                                             float X0, float Y0, float dx, float dy, int k) {
    float x = fmaf((float)k, dx, X0);
    float y = fmaf((float)k, dy, Y0);
    int xi = __float2int_rd(x);
    int yi = __float2int_rd(y);
    float wx = x - (float)xi;
    float wy = y - (float)yi;
    const __half* p = sb + yi * PITCH;
    int x0c = min(255, max(0, xi));
    int x1c = min(255, max(0, xi + 1));
    bool g0 = ((unsigned)xi < 256u);
    bool g1 = ((unsigned)(xi + 1) < 256u);
    float v00 = g0 ? __half2float(p[x0c]) : 0.0f;
    float v01 = g1 ? __half2float(p[x1c]) : 0.0f;
    float v10 = g0 ? __half2float(p[x0c + PITCH]) : 0.0f;
    float v11 = g1 ? __half2float(p[x1c + PITCH]) : 0.0f;
    float r0 = fmaf(wx, v01 - v00, v00);
    float r1 = fmaf(wx, v11 - v10, v10);
    return fmaf(wy, r1 - r0, r0);
}

__global__ __launch_bounds__(THREADS, 6)
void radon_slab_kernel(const float* __restrict__ in) {
    extern __shared__ __half simg[];

    int b     = blockIdx.x;
    int slab  = b & 3;
    int rem   = b >> 2;
    int grp   = rem % N_GROUPS;
    int batch = rem / N_GROUPS;
    int row_lo = slab * SLAB_H - 1;

    // Axis flip: for theta in [45deg,135deg] the ray is x-fast; transpose so the
    // slab axis is ALWAYS the fast axis -> |dy_eff| >= cos(45deg) for every angle.
    // Kills the straddle pathology and caps per-warp trip raggedness at 31.
    bool flipped = (grp >= 23 && grp <= 67);   // angles 46..135

    // ---- Stage slab (possibly transposed) as fp16; out-of-range rows/cols = 0 ----
    const float* img = in + (size_t)batch * IMG * IMG;
    if (!flipped) {
        for (int i = threadIdx.x; i < LROWS * IMG; i += THREADS) {
            int L = i >> 8, c = i & 255;
            int g = row_lo + L;
            float v = ((unsigned)g < (unsigned)IMG) ? img[g * IMG + c] : 0.0f;
            simg[L * PITCH + c] = __float2half_rn(v);
        }
    } else {
        for (int i = threadIdx.x; i < IMG * LROWS; i += THREADS) {
            int y = i / LROWS;
            int j = i - y * LROWS;
            int g = row_lo + j;               // original x
            float v = ((unsigned)g < (unsigned)IMG) ? img[y * IMG + g] : 0.0f;
            simg[j * PITCH + y] = __float2half_rn(v);   // stride 129 words == 1 mod 32: no conflicts
        }
    }
    __syncthreads();

    const __half* sb = simg - row_lo * PITCH;

    for (int r = threadIdx.x; r < G_ANGLES * N_DET; r += THREADS) {
        int aL = r >> 8;
        int d  = r & 255;
        int a  = grp * G_ANGLES + aL;

        float theta = (float)a * 0.017453292519943295f;
        float sn, cs;
        sincosf(theta, &sn, &cs);
        float sd = (float)d - 127.5f;
        float X0n = fmaf(sd, cs, fmaf(127.5f, sn, 127.5f));
        float Y0n = fmaf(sd, sn, fmaf(-127.5f, cs, 127.5f));
        // effective coords: swap axes when flipped (bilinear is x/y symmetric)
        float X0 = flipped ? Y0n : X0n;
        float Y0 = flipped ? X0n : Y0n;
        float dx = flipped ? cs  : -sn;
        float dy = flipped ? -sn : cs;      // |dy| >= 0.69 for all angles

        // Outer nonzero-contribution range (margins keep yi in [-1,255])
        float t0 = 0.0f, t1 = 255.0f;
        slab_clip(X0, dx, -0.999f, 255.999f, t0, t1);
        slab_clip(Y0, dy, -0.999f, 255.999f, t0, t1);
        int k0 = max(0,   iceil_c(t0));
        int k1 = min(255, ifloor_c(t1));

        // Exact y-slab partition: adjacent slabs evaluate the SAME clamped float
        // expressions -> each k claimed exactly once; +/-1-row guard absorbs ulp drift.
        {
            float inv = 1.0f / dy;          // |dy| >= 0.69, never degenerate
            if (dy > 0.0f) {
                if (slab > 0) k0 = max(k0, iceil_c(((float)(slab * SLAB_H) - Y0) * inv));
                if (slab < 3) k1 = min(k1, iceil_c(((float)((slab + 1) * SLAB_H) - Y0) * inv) - 1);
            } else {
                if (slab < 3) k0 = max(k0, ifloor_c(((float)((slab + 1) * SLAB_H) - Y0) * inv) + 1);
                if (slab > 0) k1 = min(k1, ifloor_c(((float)(slab * SLAB_H) - Y0) * inv));
            }
        }

        // x-interior: all taps valid in x -> guard-free fast loop
        float ti0 = 0.0f, ti1 = 255.0f;
        slab_clip(X0, dx, 0.002f, 254.998f, ti0, ti1);
        int ki0 = max(k0, iceil_c(ti0));
        int ki1 = min(k1, ifloor_c(ti1));
        if (ki0 > ki1) { ki0 = k1 + 1; ki1 = k1; }

        float acc = 0.0f;

        int e1 = min(ki0 - 1, k1);
        for (int k = k0; k <= e1; ++k)
            acc += edge_sample(sb, X0, Y0, dx, dy, k);

        float kf = (float)ki0;
        #pragma unroll 4
        for (int k = ki0; k <= ki1; ++k) {
            float x = fmaf(kf, dx, X0);
            float y = fmaf(kf, dy, Y0);
            kf += 1.0f;
            int xi = __float2int_rd(x);
            int yi = __float2int_rd(y);
            float wx = x - (float)xi;
            float wy = y - (float)yi;
            const __half* p = sb + yi * PITCH + xi;
            float v00 = __half2float(p[0]);
            float v01 = __half2float(p[1]);
            float v10 = __half2float(p[PITCH]);
            float v11 = __half2float(p[PITCH + 1]);
            float r0 = fmaf(wx, v01 - v00, v00);
            float r1 = fmaf(wx, v11 - v10, v10);
            acc = fmaf(wy, r1 - r0, acc + r0);
        }

        int e2 = max(ki1 + 1, k0);
        for (int k = e2; k <= k1; ++k)
            acc += edge_sample(sb, X0, Y0, dx, dy, k);

        g_scratch[slab][((size_t)batch * N_ANGLES + a) * N_DET + d] = acc;
    }
}

__global__ void radon_reduce_kernel(float* __restrict__ out) {
    int i = blockIdx.x * blockDim.x + threadIdx.x;   // float4 index
    if (i < OUT_ELEMS / 4) {
        float4 a = ((const float4*)g_scratch[0])[i];
        float4 b = ((const float4*)g_scratch[1])[i];
        float4 c = ((const float4*)g_scratch[2])[i];
        float4 d = ((const float4*)g_scratch[3])[i];
        float4 r;
        r.x = (a.x + b.x) + (c.x + d.x);
        r.y = (a.y + b.y) + (c.y + d.y);
        r.z = (a.z + b.z) + (c.z + d.z);
        r.w = (a.w + b.w) + (c.w + d.w);
        ((float4*)out)[i] = r;
    }
}

extern "C" void kernel_launch(void* const* d_in, const int* in_sizes, int n_in,
                              void* d_out, int out_size) {
    (void)in_sizes; (void)n_in; (void)out_size;
    radon_slab_kernel<<<8 * N_GROUPS * N_SLABS, THREADS, SMEM_BYTES>>>((const float*)d_in[0]);
    radon_reduce_kernel<<<(OUT_ELEMS / 4 + 255) / 256, 256>>>((float*)d_out);
}